// round 4
// baseline (speedup 1.0000x reference)
#include <cuda_runtime.h>
#include <math.h>

namespace {
constexpr int Bc = 4, Nc = 2048, Ec = 768, Hc = 12, Dc = 64;
constexpr int PAD = 68;          // smem row stride (floats), keeps float4 alignment
}

// Scratch (allocation-free rule: __device__ globals)
__device__ float g_qh[(size_t)Bc * Hc * Nc * Dc];
__device__ float g_kh[(size_t)Bc * Hc * Nc * Dc];
__device__ float g_vh[(size_t)Bc * Hc * Nc * Dc];
__device__ float g_att[(size_t)Bc * Nc * Ec];

// ---------------------------------------------------------------------------
// Kernel 1: RMSNorm + xPos RoPE + head-split transpose. One warp per (b,n,h).
// Lane holds d and d+32. Folds 1/sqrt(D) into Q.
// ---------------------------------------------------------------------------
__global__ void prep_kernel(const float* __restrict__ q, const float* __restrict__ k,
                            const float* __restrict__ v,
                            const float* __restrict__ qs, const float* __restrict__ ks) {
    int w = (blockIdx.x * blockDim.x + threadIdx.x) >> 5;
    int lane = threadIdx.x & 31;
    if (w >= Bc * Nc * Hc) return;
    int h = w % Hc;
    int bn = w / Hc;            // b*Nc + n
    int n = bn % Nc;
    int b = bn / Nc;

    size_t in_off = (size_t)bn * Ec + h * Dc;
    int d0 = lane, d1 = lane + 32;

    float q0 = q[in_off + d0], q1 = q[in_off + d1];
    float k0 = k[in_off + d0], k1 = k[in_off + d1];
    float v0 = v[in_off + d0], v1 = v[in_off + d1];

    // RMS over D=64
    float sq = q0 * q0 + q1 * q1;
    float sk = k0 * k0 + k1 * k1;
#pragma unroll
    for (int o = 16; o; o >>= 1) {
        sq += __shfl_xor_sync(0xffffffffu, sq, o);
        sk += __shfl_xor_sync(0xffffffffu, sk, o);
    }
    float qn = rsqrtf(sq * (1.0f / 64.0f) + 1e-6f);
    float kn = rsqrtf(sk * (1.0f / 64.0f) + 1e-6f);
    q0 *= qs[d0] * qn; q1 *= qs[d1] * qn;
    k0 *= ks[d0] * kn; k1 *= ks[d1] * kn;

    // xPos RoPE on dims [0,32): pairwise (2p, 2p+1) rotation. d0 = lane < 32 always.
    int p = d0 >> 1;
    double invf = pow(10000.0, -(double)p / 16.0);          // theta^-(2p/RDIM)
    double fr = (double)n * invf;
    float c = (float)cos(fr), s = (float)sin(fr);
    double base = (2.0 * p + 12.8) / 44.8;                  // (2p + 0.4*RDIM)/(1.4*RDIM)
    double pw = ((double)n - 1024.0) / 512.0;               // (t - N//2)/XPOS_SCALE_BASE
    float sc = (float)pow(base, pw);

    float qp_ = __shfl_xor_sync(0xffffffffu, q0, 1);        // pair partner
    float kp_ = __shfl_xor_sync(0xffffffffu, k0, 1);
    float sgn = (d0 & 1) ? s : -s;                          // rotate_half sign
    q0 = (q0 * c + qp_ * sgn) * sc;
    k0 = (k0 * c + kp_ * sgn) / sc;

    // fold softmax scale 1/sqrt(64) into Q
    q0 *= 0.125f; q1 *= 0.125f;

    size_t out_off = (((size_t)(b * Hc + h)) * Nc + n) * Dc;
    g_qh[out_off + d0] = q0; g_qh[out_off + d1] = q1;
    g_kh[out_off + d0] = k0; g_kh[out_off + d1] = k1;
    g_vh[out_off + d0] = v0; g_vh[out_off + d1] = v1;
}

// ---------------------------------------------------------------------------
// Kernel 2: causal flash attention, fp32. Block = 256 thr (16x16), tile 64x64.
// Qd/Kd stored d-major, Vs/Ps stored j-major -> all inner loads are LDS.128.
// ---------------------------------------------------------------------------
__global__ __launch_bounds__(256, 2) void attn_kernel() {
    extern __shared__ float sm[];
    float* Qd = sm;                 // [64][PAD] : Qd[d*PAD + row]
    float* Kd = sm + 64 * PAD;      // [64][PAD] : Kd[d*PAD + col]
    float* Vs = sm + 2 * 64 * PAD;  // [64][PAD] : Vs[j*PAD + d]
    float* Ps = sm + 3 * 64 * PAD;  // [64][PAD] : Ps[j*PAD + row]

    int qi = blockIdx.x;            // query tile
    int bh = blockIdx.y;            // b*H + h
    int b = bh / Hc, h = bh % Hc;
    int tid = threadIdx.x;
    int tx = tid & 15, ty = tid >> 4;

    size_t base = (size_t)bh * Nc * Dc;
    const float* Qg = g_qh + base + (size_t)qi * 64 * Dc;

#pragma unroll
    for (int it = 0; it < 16; it++) {
        int idx = it * 256 + tid;
        int row = idx >> 6, d = idx & 63;
        Qd[d * PAD + row] = Qg[row * Dc + d];
    }

    float m[4], l[4], acc[4][4];
#pragma unroll
    for (int r = 0; r < 4; r++) {
        m[r] = -INFINITY; l[r] = 0.f;
#pragma unroll
        for (int c = 0; c < 4; c++) acc[r][c] = 0.f;
    }

    for (int kt = 0; kt <= qi; kt++) {
        const float* Kg = g_kh + base + (size_t)kt * 64 * Dc;
        const float* Vg = g_vh + base + (size_t)kt * 64 * Dc;
#pragma unroll
        for (int it = 0; it < 16; it++) {
            int idx = it * 256 + tid;
            int row = idx >> 6, d = idx & 63;
            Kd[d * PAD + row] = Kg[row * Dc + d];
            Vs[row * PAD + d] = Vg[row * Dc + d];
        }
        __syncthreads();

        // S = Q K^T  (4x4 per thread)
        float s[4][4];
#pragma unroll
        for (int r = 0; r < 4; r++)
#pragma unroll
            for (int c = 0; c < 4; c++) s[r][c] = 0.f;
#pragma unroll 8
        for (int kk = 0; kk < 64; kk++) {
            float4 qv = *(const float4*)(Qd + kk * PAD + 4 * ty);
            float4 kv = *(const float4*)(Kd + kk * PAD + 4 * tx);
            float qa[4] = {qv.x, qv.y, qv.z, qv.w};
            float ka[4] = {kv.x, kv.y, kv.z, kv.w};
#pragma unroll
            for (int r = 0; r < 4; r++)
#pragma unroll
                for (int c = 0; c < 4; c++) s[r][c] += qa[r] * ka[c];
        }

        if (kt == qi) {  // causal mask on diagonal tile
#pragma unroll
            for (int r = 0; r < 4; r++)
#pragma unroll
                for (int c = 0; c < 4; c++)
                    if (4 * tx + c > 4 * ty + r) s[r][c] = -INFINITY;
        }

        // online softmax update (rows split across the 16 tx lanes)
#pragma unroll
        for (int r = 0; r < 4; r++) {
            float mx = fmaxf(fmaxf(s[r][0], s[r][1]), fmaxf(s[r][2], s[r][3]));
#pragma unroll
            for (int o = 8; o; o >>= 1) mx = fmaxf(mx, __shfl_xor_sync(0xffffffffu, mx, o));
            float mn = fmaxf(m[r], mx);
            float fac = __expf(m[r] - mn);
            float rs = 0.f;
#pragma unroll
            for (int c = 0; c < 4; c++) {
                float pp = __expf(s[r][c] - mn);
                s[r][c] = pp; rs += pp;
            }
#pragma unroll
            for (int o = 8; o; o >>= 1) rs += __shfl_xor_sync(0xffffffffu, rs, o);
            l[r] = l[r] * fac + rs;
            m[r] = mn;
#pragma unroll
            for (int c = 0; c < 4; c++) acc[r][c] *= fac;
        }

        // P -> smem, transposed to j-major (float4 over row index)
#pragma unroll
        for (int c = 0; c < 4; c++) {
            float4 pc = make_float4(s[0][c], s[1][c], s[2][c], s[3][c]);
            *(float4*)(Ps + (4 * tx + c) * PAD + 4 * ty) = pc;
        }
        __syncthreads();

        // O += P V
#pragma unroll 8
        for (int jj = 0; jj < 64; jj++) {
            float4 pv = *(const float4*)(Ps + jj * PAD + 4 * ty);
            float4 vv = *(const float4*)(Vs + jj * PAD + 4 * tx);
            float pa[4] = {pv.x, pv.y, pv.z, pv.w};
            float va[4] = {vv.x, vv.y, vv.z, vv.w};
#pragma unroll
            for (int r = 0; r < 4; r++)
#pragma unroll
                for (int c = 0; c < 4; c++) acc[r][c] += pa[r] * va[c];
        }
        __syncthreads();
    }

    // epilogue: normalize, write in [B,N,E] layout for the projection GEMM
    int n0 = qi * 64;
#pragma unroll
    for (int r = 0; r < 4; r++) {
        float inv = 1.f / l[r];
        int n = n0 + 4 * ty + r;
        float4 o4 = make_float4(acc[r][0] * inv, acc[r][1] * inv,
                                acc[r][2] * inv, acc[r][3] * inv);
        *(float4*)(g_att + ((size_t)(b * Nc + n)) * Ec + h * Dc + 4 * tx) = o4;
    }
}

// ---------------------------------------------------------------------------
// Kernel 3: out = att @ W^T + bias.  C[m,o] = sum_e att[m,e] * W[o,e] + b[o]
// ---------------------------------------------------------------------------
__global__ __launch_bounds__(256, 2) void proj_kernel(const float* __restrict__ W,
                                                      const float* __restrict__ bias,
                                                      float* __restrict__ out) {
    __shared__ float As[64 * PAD];  // As[e*PAD + m]
    __shared__ float Bs[64 * PAD];  // Bs[e*PAD + o]
    int m0 = blockIdx.x * 64, o0 = blockIdx.y * 64;
    int tid = threadIdx.x, tx = tid & 15, ty = tid >> 4;

    float acc[4][4] = {};
    for (int kt = 0; kt < Ec / 64; kt++) {
#pragma unroll
        for (int it = 0; it < 16; it++) {
            int idx = it * 256 + tid;
            int row = idx >> 6, e = idx & 63;
            As[e * PAD + row] = g_att[(size_t)(m0 + row) * Ec + kt * 64 + e];
            Bs[e * PAD + row] = W[(size_t)(o0 + row) * Ec + kt * 64 + e];
        }
        __syncthreads();
#pragma unroll 8
        for (int kk = 0; kk < 64; kk++) {
            float4 a4 = *(const float4*)(As + kk * PAD + 4 * ty);
            float4 w4 = *(const float4*)(Bs + kk * PAD + 4 * tx);
            float aa[4] = {a4.x, a4.y, a4.z, a4.w};
            float wa[4] = {w4.x, w4.y, w4.z, w4.w};
#pragma unroll
            for (int r = 0; r < 4; r++)
#pragma unroll
                for (int c = 0; c < 4; c++) acc[r][c] += aa[r] * wa[c];
        }
        __syncthreads();
    }

    float4 bv = *(const float4*)(bias + o0 + 4 * tx);
    float ba[4] = {bv.x, bv.y, bv.z, bv.w};
#pragma unroll
    for (int r = 0; r < 4; r++) {
        int mrow = m0 + 4 * ty + r;
        float4 o4 = make_float4(acc[r][0] + ba[0], acc[r][1] + ba[1],
                                acc[r][2] + ba[2], acc[r][3] + ba[3]);
        *(float4*)(out + (size_t)mrow * Ec + o0 + 4 * tx) = o4;
    }
}

// ---------------------------------------------------------------------------
extern "C" void kernel_launch(void* const* d_in, const int* in_sizes, int n_in,
                              void* d_out, int out_size) {
    const float* q  = (const float*)d_in[0];
    const float* k  = (const float*)d_in[1];
    const float* v  = (const float*)d_in[2];
    const float* qs = (const float*)d_in[3];
    const float* ks = (const float*)d_in[4];
    const float* pw = (const float*)d_in[5];
    const float* pb = (const float*)d_in[6];
    float* out = (float*)d_out;

    // 1) norm + rope + transpose
    prep_kernel<<<(Bc * Nc * Hc) / 8, 256>>>(q, k, v, qs, ks);

    // 2) causal flash attention
    int smem = 4 * 64 * PAD * (int)sizeof(float);  // 69632 B
    cudaFuncSetAttribute(attn_kernel, cudaFuncAttributeMaxDynamicSharedMemorySize, smem);
    attn_kernel<<<dim3(Nc / 64, Bc * Hc), 256, smem>>>();

    // 3) output projection
    proj_kernel<<<dim3((Bc * Nc) / 64, Ec / 64), 256>>>(pw, pb, out);
}